// round 10
// baseline (speedup 1.0000x reference)
#include <cuda_runtime.h>
#include <cstdint>

// ============================================================================
// out[4096,1000] = core[4096,4096] @ weights[1000,4096]^T   (fp32)
//
// R10 vs R9 (GEMM 159us @ tensor 71%): remove SMEM from the GEMM entirely.
// The fragment-major packed layout makes each warp's mma fragment a perfectly
// coalesced global load (A: LDG.128 x4, B: LDG.64 x8 per ks). Mainloop is
// LDG + HMMA only: no cp.async, no STS/LDS, no barriers, no wait_groups.
// Warps run fully decoupled; L1/L2 serve the heavy cross-warp/cross-CTA reuse.
// ============================================================================

#define MDIM 4096
#define NDIM 1000
#define KDIM 4096

#define BM 256
#define BN 128
#define BK 32
#define KTILES (KDIM / BK)            // 128
#define THREADS 256

// packed scratch: A' = [16 mtiles][128 kt][2048 x 16B], B' = [8 ntiles][128 kt][2048 x 8B]
__device__ uint4 g_Ap[16 * 128 * 2048];   // 64 MB
__device__ uint2 g_Bp[8 * 128 * 2048];    // 16 MB

// ---------------------------------------------------------------------------
__device__ __forceinline__ uint32_t f2tf(float f) {
    uint32_t r;
    asm("cvt.rna.tf32.f32 %0, %1;" : "=r"(r) : "f"(f));
    return r;
}

__device__ __forceinline__ void mma_tf32(float c[4],
                                         const uint32_t a[4], const uint32_t b[2]) {
    asm volatile(
        "mma.sync.aligned.m16n8k8.row.col.f32.tf32.tf32.f32 "
        "{%0,%1,%2,%3}, {%4,%5,%6,%7}, {%8,%9}, {%0,%1,%2,%3};"
        : "+f"(c[0]), "+f"(c[1]), "+f"(c[2]), "+f"(c[3])
        : "r"(a[0]), "r"(a[1]), "r"(a[2]), "r"(a[3]), "r"(b[0]), "r"(b[1]));
}

// ---------------------------------------------------------------------------
// Fused pack kernel (unchanged from R8/R9). Fragment-major layouts:
//   A chunk ((wm*4+t)*4+ks)*32+lane -> 16B quad {A[r,c],A[r+8,c],A[r,c+4],A[r+8,c+4]}
//   B chunk ((wn*8+u)*4+ks)*32+lane -> 8B pair {B[n,c],B[n,c+4]}, n>=1000 zeroed
// ---------------------------------------------------------------------------
__global__ void __launch_bounds__(256) pack_ab_kernel(const float* __restrict__ A,
                                                      const float* __restrict__ B) {
    const uint32_t bid = blockIdx.x;
    const uint32_t tidl = threadIdx.x;
    if (bid < 4096) {
        const uint32_t idx = bid * 256u + tidl;        // [0, 2^20)
        const uint32_t mtile = idx >> 16;
        const uint32_t ktg   = (idx >> 11) & 31u;
        const uint32_t chunk = idx & 2047u;
        const uint32_t lane  = chunk & 31u;
        const uint32_t blk   = chunk >> 5;
        const uint32_t ks    = blk & 3u;
        const uint32_t t     = (blk >> 2) & 3u;
        const uint32_t wm    = blk >> 4;
        const uint32_t r = mtile * 256 + wm * 64 + t * 16 + (lane >> 2);
        const float* rowp = A + (size_t)r * KDIM;
        #pragma unroll
        for (int j = 0; j < 4; j++) {
            const uint32_t kt = ktg * 4 + j;
            const uint32_t c  = kt * 32 + ks * 8 + (lane & 3);
            const float* p = rowp + c;
            uint4 v;
            v.x = f2tf(p[0]);
            v.y = f2tf(p[(size_t)8 * KDIM]);
            v.z = f2tf(p[4]);
            v.w = f2tf(p[(size_t)8 * KDIM + 4]);
            g_Ap[(size_t)(mtile * 128 + kt) * 2048 + chunk] = v;
        }
    } else {
        const uint32_t idx = (bid - 4096u) * 256u + tidl;  // [0, 2^19)
        const uint32_t ntile = idx >> 16;
        const uint32_t ktg   = (idx >> 11) & 31u;
        const uint32_t chunk = idx & 2047u;
        const uint32_t lane  = chunk & 31u;
        const uint32_t blk   = chunk >> 5;
        const uint32_t ks    = blk & 3u;
        const uint32_t u     = (blk >> 2) & 7u;
        const uint32_t wn    = blk >> 5;
        const uint32_t n = ntile * 128 + wn * 64 + u * 8 + (lane >> 2);
        const float* rowp = B + (size_t)n * KDIM;
        #pragma unroll
        for (int j = 0; j < 4; j++) {
            const uint32_t kt = ktg * 4 + j;
            const uint32_t c  = kt * 32 + ks * 8 + (lane & 3);
            uint2 v = make_uint2(0u, 0u);
            if (n < NDIM) {
                const float* p = rowp + c;
                v.x = f2tf(p[0]);
                v.y = f2tf(p[4]);
            }
            g_Bp[(size_t)(ntile * 128 + kt) * 2048 + chunk] = v;
        }
    }
}

// ---------------------------------------------------------------------------
__global__ void __launch_bounds__(THREADS, 1)
tol_gemm_tf32(float* __restrict__ C) {         // [4096, 1000]
    const int tid  = threadIdx.x;
    const int wid  = tid >> 5;
    const int lane = tid & 31;

    const int mtile = blockIdx.y;
    const int ntile = blockIdx.x;
    const int m0 = mtile * BM;
    const int n0 = ntile * BN;

    const int warp_m = wid >> 1;     // 0..3
    const int warp_n = wid & 1;      // 0..1

    // per-warp fragment base pointers into the packed arrays.
    //   A frag (kt, ks, t): aP + kt*2048 + (t*4 + ks)*32     (uint4, LDG.128)
    //   B frag (kt, ks, u): bP + kt*2048 + (u*4 + ks)*32     (uint2, LDG.64)
    const uint4* __restrict__ aP =
        g_Ap + ((size_t)mtile * KTILES) * 2048 + (warp_m * 16) * 32 + lane;
    const uint2* __restrict__ bP =
        g_Bp + ((size_t)ntile * KTILES) * 2048 + (warp_n * 32) * 32 + lane;

    float acc[4][8][4];
    #pragma unroll
    for (int t = 0; t < 4; t++)
        #pragma unroll
        for (int u = 0; u < 8; u++)
            #pragma unroll
            for (int i = 0; i < 4; i++)
                acc[t][u][i] = 0.0f;

    // fragment double buffers (ks granularity)
    uint32_t af[2][4][4];
    uint32_t bf[2][8][2];

#define LOAD_G(buf, aQ, bQ, ksv) do {                                            \
        _Pragma("unroll")                                                        \
        for (int t = 0; t < 4; t++) {                                            \
            uint4 v = (aQ)[(t * 4 + (ksv)) * 32];                                \
            af[buf][t][0] = v.x; af[buf][t][1] = v.y;                            \
            af[buf][t][2] = v.z; af[buf][t][3] = v.w;                            \
        }                                                                        \
        _Pragma("unroll")                                                        \
        for (int u = 0; u < 8; u++) {                                            \
            uint2 w = (bQ)[(u * 4 + (ksv)) * 32];                                \
            bf[buf][u][0] = w.x; bf[buf][u][1] = w.y;                            \
        }                                                                        \
    } while (0)

#define MMA_ALL(buf) do {                                                        \
        _Pragma("unroll")                                                        \
        for (int t = 0; t < 4; t++)                                              \
            _Pragma("unroll")                                                    \
            for (int u = 0; u < 8; u++)                                          \
                mma_tf32(acc[t][u], af[buf][t], bf[buf][u]);                     \
    } while (0)

    // prime: frag(kt0, ks0)
    LOAD_G(0, aP, bP, 0);

    for (int kt = 0; kt < KTILES - 1; kt++) {
        LOAD_G(1, aP, bP, 1);  MMA_ALL(0);
        LOAD_G(0, aP, bP, 2);  MMA_ALL(1);
        LOAD_G(1, aP, bP, 3);  MMA_ALL(0);
        aP += 2048;
        bP += 2048;
        LOAD_G(0, aP, bP, 0);  MMA_ALL(1);   // cross-kt prefetch
    }
    // last kt (no prefetch beyond the array)
    LOAD_G(1, aP, bP, 1);  MMA_ALL(0);
    LOAD_G(0, aP, bP, 2);  MMA_ALL(1);
    LOAD_G(1, aP, bP, 3);  MMA_ALL(0);
    MMA_ALL(1);

    // ---- epilogue: each warp writes its 64x64 region, guard N edge ----
    #pragma unroll
    for (int t = 0; t < 4; t++) {
        const int gr = m0 + warp_m * 64 + t * 16 + (lane >> 2);
        #pragma unroll
        for (int u = 0; u < 8; u++) {
            const int gc = n0 + warp_n * 64 + u * 8 + (lane & 3) * 2;
            if (gc < NDIM) {   // NDIM even; float2 never straddles the edge
                float2 v0 = make_float2(acc[t][u][0], acc[t][u][1]);
                float2 v1 = make_float2(acc[t][u][2], acc[t][u][3]);
                *reinterpret_cast<float2*>(C + (size_t)gr * NDIM + gc) = v0;
                *reinterpret_cast<float2*>(C + (size_t)(gr + 8) * NDIM + gc) = v1;
            }
        }
    }
}

// ---------------------------------------------------------------------------
extern "C" void kernel_launch(void* const* d_in, const int* in_sizes, int n_in,
                              void* d_out, int out_size) {
    const float* core = (const float*)d_in[0];   // [4096, 16,16,16] = [4096,4096]
    const float* wts  = (const float*)d_in[1];   // [1000, 4096]
    float* out = (float*)d_out;                  // [4096, 1000]

    // fused pack prepass (same stream -> ordered before GEMM)
    pack_ab_kernel<<<6144, 256>>>(core, wts);

    dim3 grid(8, 16, 1);   // 128 CTAs = 1 clean wave
    tol_gemm_tf32<<<grid, THREADS>>>(out);
}